// round 10
// baseline (speedup 1.0000x reference)
#include <cuda_runtime.h>

// DWTExtractor: 2-level Haar DWT + bilinear 2x upsample of level-2 details.
// Input:  (32, 1, 1024, 1024) fp32 -> Output: (32, 6, 512, 512) fp32
//          [cH1, cV1, cD1, up(cH2), up(cV2), up(cD2)]
//
// Latency-bound kernel (no pipe saturated) -> raise per-thread MLP.
// Block = one 64x64 output tile. Each thread in the central pass handles TWO
// vertically-stacked level-2 cells: 8 front-batched LDG.128 (all warp-
// contiguous 512B; NEVER pair horizontally - lane->column stays dense).
// launch_bounds(256,4) so ptxas is free up to 64 regs (no forced load
// serialization).
//  Part 0: 132-cell halo ring (clamped == jax resize weight renorm),
//          level-2 smem only, issued first to overlap with Part 1.
//  Part 1: central 32x32 level-2 cells, 2 cells/thread, 2 iterations.
//          Each cell: 4x4 patch -> level-2 coeffs to smem + 2x2 level-1
//          block to gmem (float2 streaming stores, coalesced).
//  Part 3: separable half-pixel bilinear (0.75/0.25), 8 outputs/thread,
//          vector LDS (rows 16B-aligned, stride 36), float4 streaming stores.

#define TS    64
#define H2_T  34
#define H2_S  36   // smem row stride (floats): 144B -> 16B-aligned rows

// Compute level-2 + level-1 coefficients from a loaded 4x4 patch.
__device__ __forceinline__ void patch_compute(
    const float4 v0, const float4 v1, const float4 v2, const float4 v3,
    float& l2h, float& l2v, float& l2d,
    float2& hT, float2& vT, float2& dT,
    float2& hB, float2& vB, float2& dB)
{
    const float s0l = v0.x + v0.y, d0l = v0.x - v0.y;
    const float s0r = v0.z + v0.w, d0r = v0.z - v0.w;
    const float s1l = v1.x + v1.y, d1l = v1.x - v1.y;
    const float s1r = v1.z + v1.w, d1r = v1.z - v1.w;
    const float s2l = v2.x + v2.y, d2l = v2.x - v2.y;
    const float s2r = v2.z + v2.w, d2r = v2.z - v2.w;
    const float s3l = v3.x + v3.y, d3l = v3.x - v3.y;
    const float s3r = v3.z + v3.w, d3r = v3.z - v3.w;

    const float a00 = s0l + s1l, a01 = s0r + s1r;
    const float a10 = s2l + s3l, a11 = s2r + s3r;
    l2h = (a00 - a01 + a10 - a11) * 0.25f;   // 0.5 haar * 0.5 folded cA1
    l2v = (a00 + a01 - a10 - a11) * 0.25f;
    l2d = (a00 - a01 - a10 + a11) * 0.25f;

    hT = make_float2((d0l + d1l) * 0.5f, (d0r + d1r) * 0.5f);
    vT = make_float2((s0l - s1l) * 0.5f, (s0r - s1r) * 0.5f);
    dT = make_float2((d0l - d1l) * 0.5f, (d0r - d1r) * 0.5f);
    hB = make_float2((d2l + d3l) * 0.5f, (d2r + d3r) * 0.5f);
    vB = make_float2((s2l - s3l) * 0.5f, (s2r - s3r) * 0.5f);
    dB = make_float2((d2l - d3l) * 0.5f, (d2r - d3r) * 0.5f);
}

__global__ __launch_bounds__(256, 4)
void dwt_fused_kernel(const float* __restrict__ in, float* __restrict__ out)
{
    __shared__ __align__(16) float sH[H2_T * H2_S];
    __shared__ __align__(16) float sV[H2_T * H2_S];
    __shared__ __align__(16) float sD[H2_T * H2_S];

    const int b   = blockIdx.z;
    const int oy0 = blockIdx.y * TS;
    const int ox0 = blockIdx.x * TS;
    const int tid = threadIdx.x;

    const float* __restrict__ inb  = in  + (size_t)b * 1024 * 1024;
    float* __restrict__       outb = out + (size_t)b * 6 * 512 * 512;

    const int r0g = oy0 >> 1;   // level-2 tile origin on the 256-grid
    const int c0g = ox0 >> 1;

    // ---- Part 0: halo ring (132 cells), level-2 smem only, clamped ----
    if (tid < 132) {
        int lr, lc;
        if (tid < 34)       { lr = 0;         lc = tid;        }
        else if (tid < 68)  { lr = 33;        lc = tid - 34;   }
        else if (tid < 100) { lr = tid - 67;  lc = 0;          }
        else                { lr = tid - 99;  lc = 33;         }
        const int r = min(max(r0g - 1 + lr, 0), 255);
        const int c = min(max(c0g - 1 + lc, 0), 255);

        const float4* p = (const float4*)(inb + (size_t)(4 * r) * 1024) + c;
        const float4 v0 = p[0], v1 = p[256], v2 = p[512], v3 = p[768];
        float l2h, l2v, l2d;
        float2 t0, t1, t2, t3, t4, t5;
        patch_compute(v0, v1, v2, v3, l2h, l2v, l2d, t0, t1, t2, t3, t4, t5);
        sH[lr * H2_S + lc] = l2h;
        sV[lr * H2_S + lc] = l2v;
        sD[lr * H2_S + lc] = l2d;
    }

    // ---- Part 1: central 32x32 cells, 2 vertical cells/thread ----
    float2* const o2 = (float2*)outb;
    #pragma unroll 1
    for (int it = 0; it < 2; it++) {
        const int col  = tid & 31;               // lane -> column (coalesced)
        const int rowA = (tid >> 5) + it * 8;    // 0..15
        const int rowB = rowA + 16;              // 16..31
        const int rrA = r0g + rowA;
        const int rrB = r0g + rowB;
        const int cc  = c0g + col;

        // 8 front-batched LDG.128 (independent -> MLP 8)
        const float4* pA = (const float4*)(inb + (size_t)(4 * rrA) * 1024) + cc;
        const float4* pB = (const float4*)(inb + (size_t)(4 * rrB) * 1024) + cc;
        const float4 a0 = pA[0], a1 = pA[256], a2 = pA[512], a3 = pA[768];
        const float4 b0 = pB[0], b1 = pB[256], b2 = pB[512], b3 = pB[768];

        float l2h, l2v, l2d;
        float2 hT, vT, dT, hB, vB, dB;

        // cell A
        patch_compute(a0, a1, a2, a3, l2h, l2v, l2d, hT, vT, dT, hB, vB, dB);
        sH[(rowA + 1) * H2_S + col + 1] = l2h;
        sV[(rowA + 1) * H2_S + col + 1] = l2v;
        sD[(rowA + 1) * H2_S + col + 1] = l2d;
        {
            const size_t oT = ((size_t)(2 * rrA) * 512 + 2 * cc) >> 1;
            const size_t oB = oT + 256;
            __stcs(o2 + 0 * 131072 + oT, hT);
            __stcs(o2 + 0 * 131072 + oB, hB);
            __stcs(o2 + 1 * 131072 + oT, vT);
            __stcs(o2 + 1 * 131072 + oB, vB);
            __stcs(o2 + 2 * 131072 + oT, dT);
            __stcs(o2 + 2 * 131072 + oB, dB);
        }

        // cell B
        patch_compute(b0, b1, b2, b3, l2h, l2v, l2d, hT, vT, dT, hB, vB, dB);
        sH[(rowB + 1) * H2_S + col + 1] = l2h;
        sV[(rowB + 1) * H2_S + col + 1] = l2v;
        sD[(rowB + 1) * H2_S + col + 1] = l2d;
        {
            const size_t oT = ((size_t)(2 * rrB) * 512 + 2 * cc) >> 1;
            const size_t oB = oT + 256;
            __stcs(o2 + 0 * 131072 + oT, hT);
            __stcs(o2 + 0 * 131072 + oB, hB);
            __stcs(o2 + 1 * 131072 + oT, vT);
            __stcs(o2 + 1 * 131072 + oB, vB);
            __stcs(o2 + 2 * 131072 + oT, dT);
            __stcs(o2 + 2 * 131072 + oB, dB);
        }
    }

    __syncthreads();

    // ---- Part 3: bilinear 2x upsample, 8 horizontal outputs/thread ----
    // out[2k] = 0.25*v[k-1]+0.75*v[k],  out[2k+1] = 0.75*v[k]+0.25*v[k+1]
    #pragma unroll 1
    for (int i = tid; i < 512; i += 256) {
        const int y  = i >> 3;         // 0..63
        const int xo = i & 7;          // col group: x = 8*xo .. 8*xo+7
        const int ky = (y >> 1) + 1;
        const int ry0 = (y & 1) ? ky     : ky - 1;
        const int ry1 = (y & 1) ? ky + 1 : ky;
        const float wy0 = (y & 1) ? 0.75f : 0.25f;
        const float wy1 = 1.0f - wy0;

        const int cb = 4 * xo;               // local level-2 cols cb..cb+5
        const int A0 = ry0 * H2_S + cb;      // 16B-aligned
        const int A1 = ry1 * H2_S + cb;

        const size_t o4 = ((size_t)(oy0 + y) * 512 + ox0 + 8 * xo) >> 2;
        float4* op = (float4*)outb;

        #pragma unroll
        for (int ch = 0; ch < 3; ch++) {
            const float* s = (ch == 0) ? sH : (ch == 1) ? sV : sD;
            const float4 a4 = *(const float4*)(s + A0);
            const float2 a2 = *(const float2*)(s + A0 + 4);
            const float4 b4 = *(const float4*)(s + A1);
            const float2 b2 = *(const float2*)(s + A1 + 4);
            const float m0 = wy0 * a4.x + wy1 * b4.x;
            const float m1 = wy0 * a4.y + wy1 * b4.y;
            const float m2 = wy0 * a4.z + wy1 * b4.z;
            const float m3 = wy0 * a4.w + wy1 * b4.w;
            const float m4 = wy0 * a2.x + wy1 * b2.x;
            const float m5 = wy0 * a2.y + wy1 * b2.y;

            const float4 r0 = make_float4(0.25f * m0 + 0.75f * m1,
                                          0.75f * m1 + 0.25f * m2,
                                          0.25f * m1 + 0.75f * m2,
                                          0.75f * m2 + 0.25f * m3);
            const float4 r1 = make_float4(0.25f * m2 + 0.75f * m3,
                                          0.75f * m3 + 0.25f * m4,
                                          0.25f * m3 + 0.75f * m4,
                                          0.75f * m4 + 0.25f * m5);
            __stcs(op + (size_t)(3 + ch) * 65536 + o4,     r0);
            __stcs(op + (size_t)(3 + ch) * 65536 + o4 + 1, r1);
        }
    }
}

extern "C" void kernel_launch(void* const* d_in, const int* in_sizes, int n_in,
                              void* d_out, int out_size)
{
    const float* x = (const float*)d_in[0];
    float* out = (float*)d_out;
    dim3 grid(512 / TS, 512 / TS, 32);   // (8, 8, 32) = 2048 blocks
    dwt_fused_kernel<<<grid, 256>>>(x, out);
}

// round 11
// speedup vs baseline: 1.1208x; 1.1208x over previous
#include <cuda_runtime.h>

// DWTExtractor: 2-level Haar DWT + bilinear 2x upsample of level-2 details.
// Input:  (32, 1, 1024, 1024) fp32 -> Output: (32, 6, 512, 512) fp32
//          [cH1, cV1, cD1, up(cH2), up(cV2), up(cD2)]
//
// Champion structure (R3): block = one 64x64 output tile, all 6 channels.
//   Merged phase: single loop over the 34x34 level-2 grid (incl. 1-halo,
//     clamped indices == jax resize weight renormalization). Each cell loads
//     its 4x4 input patch once (4 x LDG.128, coalesced across lanes),
//     produces level-2 coeffs -> smem, and for central cells the 2x2
//     level-1 detail block -> gmem (float2 streaming stores).
//   (one __syncthreads)
//   Part 3 (ONLY change vs champion): vectorized bilinear upsample --
//     8 outputs/thread, LDS.128/LDS.64 from 16B-aligned smem rows
//     (stride 36), float4 streaming stores.

#define TS    64
#define H2_T  34
#define H2_S  36   // smem row stride (floats): 144B -> 16B-aligned rows

__global__ __launch_bounds__(256, 6)
void dwt_fused_kernel(const float* __restrict__ in, float* __restrict__ out)
{
    __shared__ __align__(16) float sH[H2_T * H2_S];
    __shared__ __align__(16) float sV[H2_T * H2_S];
    __shared__ __align__(16) float sD[H2_T * H2_S];

    const int b   = blockIdx.z;
    const int oy0 = blockIdx.y * TS;
    const int ox0 = blockIdx.x * TS;
    const int tid = threadIdx.x;

    const float* __restrict__ inb  = in  + (size_t)b * 1024 * 1024;
    float* __restrict__       outb = out + (size_t)b * 6 * 512 * 512;

    // ---- Merged phase: level-2 (34x34 w/ halo) + level-1 (central) ----
    const int r0g = oy0 >> 1;   // level-2 tile origin on the 256-grid
    const int c0g = ox0 >> 1;
    #pragma unroll 1
    for (int i = tid; i < H2_T * H2_T; i += 256) {
        const int lr = i / H2_T;
        const int lc = i - lr * H2_T;
        const int rr = r0g - 1 + lr;
        const int cc = c0g - 1 + lc;
        const int r = min(max(rr, 0), 255);   // clamp only bites on halo cells
        const int c = min(max(cc, 0), 255);

        const float4 v0 = *((const float4*)(inb + (size_t)(4 * r    ) * 1024) + c);
        const float4 v1 = *((const float4*)(inb + (size_t)(4 * r + 1) * 1024) + c);
        const float4 v2 = *((const float4*)(inb + (size_t)(4 * r + 2) * 1024) + c);
        const float4 v3 = *((const float4*)(inb + (size_t)(4 * r + 3) * 1024) + c);

        // per-row horizontal sums/diffs
        const float s0l = v0.x + v0.y, d0l = v0.x - v0.y;
        const float s0r = v0.z + v0.w, d0r = v0.z - v0.w;
        const float s1l = v1.x + v1.y, d1l = v1.x - v1.y;
        const float s1r = v1.z + v1.w, d1r = v1.z - v1.w;
        const float s2l = v2.x + v2.y, d2l = v2.x - v2.y;
        const float s2r = v2.z + v2.w, d2r = v2.z - v2.w;
        const float s3l = v3.x + v3.y, d3l = v3.x - v3.y;
        const float s3r = v3.z + v3.w, d3r = v3.z - v3.w;

        // 2*cA1 quad
        const float a00 = s0l + s1l, a01 = s0r + s1r;
        const float a10 = s2l + s3l, a11 = s2r + s3r;

        // level-2 coeffs: 0.5 (haar) * 0.5 (cA1 factor folded) = 0.25
        sH[lr * H2_S + lc] = (a00 - a01 + a10 - a11) * 0.25f;
        sV[lr * H2_S + lc] = (a00 + a01 - a10 - a11) * 0.25f;
        sD[lr * H2_S + lc] = (a00 - a01 - a10 + a11) * 0.25f;

        // central cells: emit the 2x2 level-1 detail block (rows 2rr, 2rr+1;
        // cols 2cc, 2cc+1 on the 512-grid). lr,lc in [1,32] <=> unclamped.
        if ((unsigned)(lr - 1) < 32u && (unsigned)(lc - 1) < 32u) {
            const float2 hT = make_float2((d0l + d1l) * 0.5f, (d0r + d1r) * 0.5f);
            const float2 vT = make_float2((s0l - s1l) * 0.5f, (s0r - s1r) * 0.5f);
            const float2 dT = make_float2((d0l - d1l) * 0.5f, (d0r - d1r) * 0.5f);
            const float2 hB = make_float2((d2l + d3l) * 0.5f, (d2r + d3r) * 0.5f);
            const float2 vB = make_float2((s2l - s3l) * 0.5f, (s2r - s3r) * 0.5f);
            const float2 dB = make_float2((d2l - d3l) * 0.5f, (d2r - d3r) * 0.5f);

            const size_t oT = ((size_t)(2 * rr) * 512 + 2 * cc) >> 1;  // float2 idx
            const size_t oB = oT + 256;                                 // next row
            float2* o2 = (float2*)outb;
            __stcs(o2 + 0 * 131072 + oT, hT);
            __stcs(o2 + 0 * 131072 + oB, hB);
            __stcs(o2 + 1 * 131072 + oT, vT);
            __stcs(o2 + 1 * 131072 + oB, vB);
            __stcs(o2 + 2 * 131072 + oT, dT);
            __stcs(o2 + 2 * 131072 + oB, dB);
        }
    }

    __syncthreads();

    // ---- Part 3: bilinear 2x upsample, 8 horizontal outputs/thread ----
    // out[2k] = 0.25*v[k-1]+0.75*v[k],  out[2k+1] = 0.75*v[k]+0.25*v[k+1]
    #pragma unroll 1
    for (int i = tid; i < 512; i += 256) {
        const int y  = i >> 3;         // 0..63
        const int xo = i & 7;          // col group: x = 8*xo .. 8*xo+7
        const int ky = (y >> 1) + 1;
        const int ry0 = (y & 1) ? ky     : ky - 1;
        const int ry1 = (y & 1) ? ky + 1 : ky;
        const float wy0 = (y & 1) ? 0.75f : 0.25f;
        const float wy1 = 1.0f - wy0;

        const int cb = 4 * xo;               // local level-2 cols cb..cb+5
        const int A0 = ry0 * H2_S + cb;      // 16B-aligned
        const int A1 = ry1 * H2_S + cb;

        const size_t o4 = ((size_t)(oy0 + y) * 512 + ox0 + 8 * xo) >> 2;
        float4* op = (float4*)outb;

        #pragma unroll
        for (int ch = 0; ch < 3; ch++) {
            const float* s = (ch == 0) ? sH : (ch == 1) ? sV : sD;
            const float4 a4 = *(const float4*)(s + A0);
            const float2 a2 = *(const float2*)(s + A0 + 4);
            const float4 b4 = *(const float4*)(s + A1);
            const float2 b2 = *(const float2*)(s + A1 + 4);
            const float m0 = wy0 * a4.x + wy1 * b4.x;
            const float m1 = wy0 * a4.y + wy1 * b4.y;
            const float m2 = wy0 * a4.z + wy1 * b4.z;
            const float m3 = wy0 * a4.w + wy1 * b4.w;
            const float m4 = wy0 * a2.x + wy1 * b2.x;
            const float m5 = wy0 * a2.y + wy1 * b2.y;

            const float4 r0 = make_float4(0.25f * m0 + 0.75f * m1,
                                          0.75f * m1 + 0.25f * m2,
                                          0.25f * m1 + 0.75f * m2,
                                          0.75f * m2 + 0.25f * m3);
            const float4 r1 = make_float4(0.25f * m2 + 0.75f * m3,
                                          0.75f * m3 + 0.25f * m4,
                                          0.25f * m3 + 0.75f * m4,
                                          0.75f * m4 + 0.25f * m5);
            __stcs(op + (size_t)(3 + ch) * 65536 + o4,     r0);
            __stcs(op + (size_t)(3 + ch) * 65536 + o4 + 1, r1);
        }
    }
}

extern "C" void kernel_launch(void* const* d_in, const int* in_sizes, int n_in,
                              void* d_out, int out_size)
{
    const float* x = (const float*)d_in[0];
    float* out = (float*)d_out;
    dim3 grid(512 / TS, 512 / TS, 32);   // (8, 8, 32) = 2048 blocks
    dwt_fused_kernel<<<grid, 256>>>(x, out);
}

// round 12
// speedup vs baseline: 1.2832x; 1.1449x over previous
#include <cuda_runtime.h>

// DWTExtractor: 2-level Haar DWT + bilinear 2x upsample of level-2 details.
// Input:  (32, 1, 1024, 1024) fp32 -> Output: (32, 6, 512, 512) fp32
//          [cH1, cV1, cD1, up(cH2), up(cV2), up(cD2)]
//
// Champion structure (R3), tile shrunk 64x64 -> 32x32 to cut wave-quantization
// waste: 8192 blocks / 888 concurrent = 9.2 waves (tail ~8%) vs 2048 blocks =
// 2.31 waves (tail ~23%). Per-block logic unchanged:
//   Merged phase: loop over the 18x18 level-2 grid (incl. 1-halo, clamped
//     indices == jax resize weight renormalization). Each cell loads its 4x4
//     input patch once (4 x LDG.128, lanes -> consecutive float4 columns),
//     emits level-2 coeffs -> smem and, for the central 16x16 cells, the 2x2
//     level-1 detail block -> gmem (float2 streaming stores).
//   (one __syncthreads)
//   Part 3: scalar separable half-pixel bilinear (0.75/0.25), 4 outputs per
//     thread, one iteration, float4 streaming stores. (Vector-LDS variant
//     measured SLOWER in R10 -- keep scalar.)

#define TS    32
#define H2_T  18
#define H2_S  19

__global__ __launch_bounds__(256, 6)
void dwt_fused_kernel(const float* __restrict__ in, float* __restrict__ out)
{
    __shared__ float sH[H2_T * H2_S];
    __shared__ float sV[H2_T * H2_S];
    __shared__ float sD[H2_T * H2_S];

    const int b   = blockIdx.z;
    const int oy0 = blockIdx.y * TS;
    const int ox0 = blockIdx.x * TS;
    const int tid = threadIdx.x;

    const float* __restrict__ inb  = in  + (size_t)b * 1024 * 1024;
    float* __restrict__       outb = out + (size_t)b * 6 * 512 * 512;

    // ---- Merged phase: level-2 (18x18 w/ halo) + level-1 (central 16x16) ----
    const int r0g = oy0 >> 1;   // level-2 tile origin on the 256-grid
    const int c0g = ox0 >> 1;
    #pragma unroll 1
    for (int i = tid; i < H2_T * H2_T; i += 256) {
        const int lr = i / H2_T;
        const int lc = i - lr * H2_T;
        const int rr = r0g - 1 + lr;
        const int cc = c0g - 1 + lc;
        const int r = min(max(rr, 0), 255);   // clamp only bites on halo cells
        const int c = min(max(cc, 0), 255);

        const float4 v0 = *((const float4*)(inb + (size_t)(4 * r    ) * 1024) + c);
        const float4 v1 = *((const float4*)(inb + (size_t)(4 * r + 1) * 1024) + c);
        const float4 v2 = *((const float4*)(inb + (size_t)(4 * r + 2) * 1024) + c);
        const float4 v3 = *((const float4*)(inb + (size_t)(4 * r + 3) * 1024) + c);

        // per-row horizontal sums/diffs
        const float s0l = v0.x + v0.y, d0l = v0.x - v0.y;
        const float s0r = v0.z + v0.w, d0r = v0.z - v0.w;
        const float s1l = v1.x + v1.y, d1l = v1.x - v1.y;
        const float s1r = v1.z + v1.w, d1r = v1.z - v1.w;
        const float s2l = v2.x + v2.y, d2l = v2.x - v2.y;
        const float s2r = v2.z + v2.w, d2r = v2.z - v2.w;
        const float s3l = v3.x + v3.y, d3l = v3.x - v3.y;
        const float s3r = v3.z + v3.w, d3r = v3.z - v3.w;

        // 2*cA1 quad
        const float a00 = s0l + s1l, a01 = s0r + s1r;
        const float a10 = s2l + s3l, a11 = s2r + s3r;

        // level-2 coeffs: 0.5 (haar) * 0.5 (cA1 factor folded) = 0.25
        sH[lr * H2_S + lc] = (a00 - a01 + a10 - a11) * 0.25f;
        sV[lr * H2_S + lc] = (a00 + a01 - a10 - a11) * 0.25f;
        sD[lr * H2_S + lc] = (a00 - a01 - a10 + a11) * 0.25f;

        // central cells: emit the 2x2 level-1 detail block (rows 2rr, 2rr+1;
        // cols 2cc, 2cc+1 on the 512-grid). lr,lc in [1,16] <=> unclamped.
        if ((unsigned)(lr - 1) < 16u && (unsigned)(lc - 1) < 16u) {
            const float2 hT = make_float2((d0l + d1l) * 0.5f, (d0r + d1r) * 0.5f);
            const float2 vT = make_float2((s0l - s1l) * 0.5f, (s0r - s1r) * 0.5f);
            const float2 dT = make_float2((d0l - d1l) * 0.5f, (d0r - d1r) * 0.5f);
            const float2 hB = make_float2((d2l + d3l) * 0.5f, (d2r + d3r) * 0.5f);
            const float2 vB = make_float2((s2l - s3l) * 0.5f, (s2r - s3r) * 0.5f);
            const float2 dB = make_float2((d2l - d3l) * 0.5f, (d2r - d3r) * 0.5f);

            const size_t oT = (size_t)(2 * rr) * 256 + cc;   // float2 index
            const size_t oB = oT + 256;                      // next row
            float2* o2 = (float2*)outb;
            __stcs(o2 + 0 * 131072 + oT, hT);
            __stcs(o2 + 0 * 131072 + oB, hB);
            __stcs(o2 + 1 * 131072 + oT, vT);
            __stcs(o2 + 1 * 131072 + oB, vB);
            __stcs(o2 + 2 * 131072 + oT, dT);
            __stcs(o2 + 2 * 131072 + oB, dB);
        }
    }

    __syncthreads();

    // ---- Part 3: half-pixel bilinear 2x, 4 horizontally-adjacent outputs ----
    // out[2k] = 0.25*v[k-1]+0.75*v[k],  out[2k+1] = 0.75*v[k]+0.25*v[k+1]
    {
        const int i  = tid;            // 256 items, exactly one iteration
        const int y  = i >> 3;         // 0..31
        const int xq = i & 7;          // group of 4 cols
        const int ky = (y >> 1) + 1;   // local level-2 row of k
        const int ry0 = (y & 1) ? ky     : ky - 1;
        const int ry1 = (y & 1) ? ky + 1 : ky;
        const float wy0 = (y & 1) ? 0.75f : 0.25f;
        const float wy1 = 1.0f - wy0;

        const int cb = 2 * xq;         // local level-2 cols cb..cb+3 used
        const int A0 = ry0 * H2_S + cb;
        const int A1 = ry1 * H2_S + cb;

        float4 hv, vv, dv;
        {
            const float m0 = wy0 * sH[A0    ] + wy1 * sH[A1    ];
            const float m1 = wy0 * sH[A0 + 1] + wy1 * sH[A1 + 1];
            const float m2 = wy0 * sH[A0 + 2] + wy1 * sH[A1 + 2];
            const float m3 = wy0 * sH[A0 + 3] + wy1 * sH[A1 + 3];
            hv.x = 0.25f * m0 + 0.75f * m1;
            hv.y = 0.75f * m1 + 0.25f * m2;
            hv.z = 0.25f * m1 + 0.75f * m2;
            hv.w = 0.75f * m2 + 0.25f * m3;
        }
        {
            const float m0 = wy0 * sV[A0    ] + wy1 * sV[A1    ];
            const float m1 = wy0 * sV[A0 + 1] + wy1 * sV[A1 + 1];
            const float m2 = wy0 * sV[A0 + 2] + wy1 * sV[A1 + 2];
            const float m3 = wy0 * sV[A0 + 3] + wy1 * sV[A1 + 3];
            vv.x = 0.25f * m0 + 0.75f * m1;
            vv.y = 0.75f * m1 + 0.25f * m2;
            vv.z = 0.25f * m1 + 0.75f * m2;
            vv.w = 0.75f * m2 + 0.25f * m3;
        }
        {
            const float m0 = wy0 * sD[A0    ] + wy1 * sD[A1    ];
            const float m1 = wy0 * sD[A0 + 1] + wy1 * sD[A1 + 1];
            const float m2 = wy0 * sD[A0 + 2] + wy1 * sD[A1 + 2];
            const float m3 = wy0 * sD[A0 + 3] + wy1 * sD[A1 + 3];
            dv.x = 0.25f * m0 + 0.75f * m1;
            dv.y = 0.75f * m1 + 0.25f * m2;
            dv.z = 0.25f * m1 + 0.75f * m2;
            dv.w = 0.75f * m2 + 0.25f * m3;
        }

        const size_t o4 = ((size_t)(oy0 + y) * 512 + ox0 + 4 * xq) >> 2;
        __stcs((float4*)outb + 3 * 65536 + o4, hv);
        __stcs((float4*)outb + 4 * 65536 + o4, vv);
        __stcs((float4*)outb + 5 * 65536 + o4, dv);
    }
}

extern "C" void kernel_launch(void* const* d_in, const int* in_sizes, int n_in,
                              void* d_out, int out_size)
{
    const float* x = (const float*)d_in[0];
    float* out = (float*)d_out;
    dim3 grid(512 / TS, 512 / TS, 32);   // (16, 16, 32) = 8192 blocks
    dwt_fused_kernel<<<grid, 256>>>(x, out);
}